// round 15
// baseline (speedup 1.0000x reference)
#include <cuda_runtime.h>
#include <cuda_fp16.h>
#include <math.h>
#include <stdint.h>

// Problem constants
#define D_MODEL   1024
#define NUM_HEADS 16
#define DK        64
#define B_        2
#define S_        2048
#define M_ROWS    (B_ * S_)   // 4096
#define WSZ       ((size_t)D_MODEL * D_MODEL)

// ===========================================================================
// Scratch (__device__ globals, allocation-free) — fp16
// ===========================================================================
__device__ __align__(128) __half g_xf [(size_t)M_ROWS * D_MODEL];
__device__ __align__(128) __half g_Whi[4][WSZ];
__device__ __align__(128) __half g_Wlo[4][WSZ];
__device__ __align__(128) __half g_Af [(size_t)M_ROWS * D_MODEL];

__device__ __align__(128) __half g_Qhi[(size_t)M_ROWS * D_MODEL];
__device__ __align__(128) __half g_Qlo[(size_t)M_ROWS * D_MODEL];
__device__ __align__(128) __half g_Kf [(size_t)M_ROWS * D_MODEL];
__device__ __align__(128) __half g_Vf [(size_t)M_ROWS * D_MODEL];

// ===========================================================================
// helpers
// ===========================================================================
__device__ __forceinline__ uint32_t smem_u32(const void* p) {
    uint32_t a;
    asm("{ .reg .u64 t; cvta.to.shared.u64 t, %1; cvt.u32.u64 %0, t; }"
        : "=r"(a) : "l"(p));
    return a;
}
__device__ __forceinline__ void cp_async16(uint32_t dst, const void* src) {
    uint64_t gsrc = __cvta_generic_to_global(src);
    asm volatile("cp.async.cg.shared.global [%0], [%1], 16;" :: "r"(dst), "l"(gsrc));
}
__device__ __forceinline__ void cp_async_commit() {
    asm volatile("cp.async.commit_group;" ::: "memory");
}
template <int N>
__device__ __forceinline__ void cp_async_wait() {
    asm volatile("cp.async.wait_group %0;" :: "n"(N) : "memory");
}
__device__ __forceinline__ void ldsm_x4(uint32_t r[4], uint32_t addr) {
    asm volatile("ldmatrix.sync.aligned.m8n8.x4.shared.b16 {%0,%1,%2,%3}, [%4];"
                 : "=r"(r[0]), "=r"(r[1]), "=r"(r[2]), "=r"(r[3]) : "r"(addr));
}
__device__ __forceinline__ void ldsm_x4_t(uint32_t r[4], uint32_t addr) {
    asm volatile("ldmatrix.sync.aligned.m8n8.x4.trans.shared.b16 {%0,%1,%2,%3}, [%4];"
                 : "=r"(r[0]), "=r"(r[1]), "=r"(r[2]), "=r"(r[3]) : "r"(addr));
}
// fp16 inputs, fp32 accumulate
__device__ __forceinline__ void mma16816f(float c[4], const uint32_t a[4], const uint32_t b[2]) {
    asm volatile("mma.sync.aligned.m16n8k16.row.col.f32.f16.f16.f32 "
                 "{%0,%1,%2,%3}, {%4,%5,%6,%7}, {%8,%9}, {%0,%1,%2,%3};"
                 : "+f"(c[0]), "+f"(c[1]), "+f"(c[2]), "+f"(c[3])
                 : "r"(a[0]), "r"(a[1]), "r"(a[2]), "r"(a[3]), "r"(b[0]), "r"(b[1]));
}
// fp16 inputs, fp16 accumulate (lo-residual passes)
__device__ __forceinline__ void mma16816h(uint32_t c[2], const uint32_t a[4], const uint32_t b[2]) {
    asm volatile("mma.sync.aligned.m16n8k16.row.col.f16.f16.f16.f16 "
                 "{%0,%1}, {%2,%3,%4,%5}, {%6,%7}, {%0,%1};"
                 : "+r"(c[0]), "+r"(c[1])
                 : "r"(a[0]), "r"(a[1]), "r"(a[2]), "r"(a[3]), "r"(b[0]), "r"(b[1]));
}
__device__ __forceinline__ uint32_t pack_f16(float x, float y) {
    __half2 h = __float22half2_rn(make_float2(x, y));
    return *reinterpret_cast<uint32_t*>(&h);
}
__device__ __forceinline__ void pack_hl_f16(float x, float y, uint32_t& hv, uint32_t& lv) {
    __half2 h = __float22half2_rn(make_float2(x, y));
    float2 hf = __half22float2(h);
    __half2 l = __float22half2_rn(make_float2(x - hf.x, y - hf.y));
    hv = *reinterpret_cast<uint32_t*>(&h);
    lv = *reinterpret_cast<uint32_t*>(&l);
}
__device__ __forceinline__ float2 unpack_h2(uint32_t u) {
    return __half22float2(*reinterpret_cast<__half2*>(&u));
}

// ===========================================================================
// merged fp32 -> fp16 split for x (single) + 4 weights (hi/lo), one launch
// ===========================================================================
#define NX4 (1 << 20)
#define NW4 (1 << 18)

__global__ __launch_bounds__(256)
void split_all(const float* __restrict__ x,
               const float* __restrict__ Wq, const float* __restrict__ Wk,
               const float* __restrict__ Wv, const float* __restrict__ Wo,
               __half* __restrict__ xf,
               __half* __restrict__ Whi, __half* __restrict__ Wlo)
{
    int i = blockIdx.x * 256 + threadIdx.x;
    if (i < NX4) {
        float4 v = ((const float4*)x)[i];
        ((uint32_t*)xf)[i * 2 + 0] = pack_f16(v.x, v.y);
        ((uint32_t*)xf)[i * 2 + 1] = pack_f16(v.z, v.w);
    } else {
        int j = i - NX4;
        int w = j >> 18;
        int idx = j & (NW4 - 1);
        const float* in = (w == 0) ? Wq : (w == 1) ? Wk : (w == 2) ? Wv : Wo;
        __half* hi = Whi + (size_t)w * WSZ;
        __half* lo = Wlo + (size_t)w * WSZ;
        float4 v = ((const float4*)in)[idx];
        uint32_t h01, l01, h23, l23;
        pack_hl_f16(v.x, v.y, h01, l01);
        pack_hl_f16(v.z, v.w, h23, l23);
        ((uint32_t*)hi)[idx * 2 + 0] = h01;
        ((uint32_t*)hi)[idx * 2 + 1] = h23;
        ((uint32_t*)lo)[idx * 2 + 0] = l01;
        ((uint32_t*)lo)[idx * 2 + 1] = l23;
    }
}

// ===========================================================================
// Raw mma.sync fp16x2 GEMM — block 256x128, 512 thr (16 warps, 4m x 4n),
// warp tile 64x32, BK=32, 3-stage cp.async, ONE barrier per chunk.
// hi pass: f32 accumulate. lo pass: f16 accumulate (folded each chunk).
// ===========================================================================
#define BM 256
#define BN 128
#define BK 32
#define GP 80
#define A_MAT (BM * GP)                 // 20480
#define B_MAT (BN * GP)                 // 10240
#define STG_BYTES (A_MAT + 2 * B_MAT)   // 40960
#define OFF_B A_MAT
#define SMEM_G3 (3 * STG_BYTES)         // 122880
#define NSTGK (D_MODEL / BK)            // 32

#define GEMM_MAINLOOP(Af_, Bhi_, Blo_)                                          \
    float acc[4][4][4];                                                         \
    _Pragma("unroll") for (int i = 0; i < 4; i++)                               \
        _Pragma("unroll") for (int j = 0; j < 4; j++)                           \
            _Pragma("unroll") for (int e = 0; e < 4; e++) acc[i][j][e] = 0.f;   \
    auto load_stage = [&](int c, int s) {                                       \
        const int k0 = c * BK;                                                  \
        const uint32_t st = sbase + s * STG_BYTES;                              \
        _Pragma("unroll") for (int u = 0; u < 2; u++) {                         \
            int wi = tid + u * 512;                                             \
            int r  = wi >> 2;                                                   \
            int c8 = wi & 3;                                                    \
            size_t ga = (size_t)(m0 + r) * D_MODEL + k0 + c8 * 8;               \
            cp_async16(st + (uint32_t)(r * GP + c8 * 16), (Af_) + ga);          \
        }                                                                       \
        _Pragma("unroll") for (int u = 0; u < 2; u++) {                         \
            int idx = tid + u * 512;                                            \
            int mat = idx >> 9;                                                 \
            int wi  = idx & 511;                                                \
            int r   = wi >> 2;                                                  \
            int c8  = wi & 3;                                                   \
            size_t gb = (size_t)(n0 + r) * D_MODEL + k0 + c8 * 8;               \
            cp_async16(st + OFF_B + mat * B_MAT + (uint32_t)(r * GP + c8 * 16), \
                       (mat == 0 ? (Bhi_) : (Blo_)) + gb);                      \
        }                                                                       \
        cp_async_commit();                                                      \
    };                                                                          \
    load_stage(0, 0);                                                           \
    load_stage(1, 1);                                                           \
    for (int c = 0; c < NSTGK; c++) {                                           \
        const int s = c % 3;                                                    \
        if (c + 1 < NSTGK) cp_async_wait<1>(); else cp_async_wait<0>();         \
        __syncthreads();                                                        \
        if (c + 2 < NSTGK) load_stage(c + 2, (c + 2) % 3);                      \
        const uint32_t aB = sbase + s * STG_BYTES;                              \
        const uint32_t bB = aB + OFF_B;                                         \
        uint32_t accLo[4][4][2];                                                \
        _Pragma("unroll") for (int i = 0; i < 4; i++)                           \
            _Pragma("unroll") for (int j = 0; j < 4; j++) {                     \
                accLo[i][j][0] = 0u; accLo[i][j][1] = 0u;                       \
            }                                                                   \
        _Pragma("unroll") for (int ks = 0; ks < 2; ks++) {                      \
            uint32_t af[4][4];                                                  \
            _Pragma("unroll") for (int i = 0; i < 4; i++) {                     \
                uint32_t ar = aB + (uint32_t)(warp_m * 64 + i * 16              \
                               + ((g & 1) << 3) + li) * GP                      \
                               + ks * 32 + ((uint32_t)(g >> 1) << 4);           \
                ldsm_x4(af[i], ar);                                             \
            }                                                                   \
            _Pragma("unroll") for (int j4 = 0; j4 < 2; j4++) {                  \
                uint32_t bh4[4], bl4[4];                                        \
                uint32_t br = bB + (uint32_t)(warp_n * 32 + j4 * 16             \
                               + ((g >> 1) << 3) + li) * GP                     \
                               + ks * 32 + ((uint32_t)(g & 1) << 4);            \
                ldsm_x4(bh4, br);                                               \
                ldsm_x4(bl4, br + B_MAT);                                       \
                _Pragma("unroll") for (int i = 0; i < 4; i++) {                 \
                    mma16816f(acc[i][2 * j4],       af[i], bh4 + 0);            \
                    mma16816f(acc[i][2 * j4 + 1],   af[i], bh4 + 2);            \
                    mma16816h(accLo[i][2 * j4],     af[i], bl4 + 0);            \
                    mma16816h(accLo[i][2 * j4 + 1], af[i], bl4 + 2);            \
                }                                                               \
            }                                                                   \
        }                                                                       \
        _Pragma("unroll") for (int i = 0; i < 4; i++)                           \
            _Pragma("unroll") for (int j = 0; j < 4; j++) {                     \
                float2 f0 = unpack_h2(accLo[i][j][0]);                          \
                float2 f1 = unpack_h2(accLo[i][j][1]);                          \
                acc[i][j][0] += f0.x; acc[i][j][1] += f0.y;                     \
                acc[i][j][2] += f1.x; acc[i][j][3] += f1.y;                     \
            }                                                                   \
    }

// --------------------------------------------------------------------------
// fused QKV projection: grid (8, 16, 3)
// --------------------------------------------------------------------------
__global__ void __launch_bounds__(512, 1)
gemm_qkv(const __half* __restrict__ Af, const __half* __restrict__ Whi_all,
         const __half* __restrict__ Wlo_all,
         __half* __restrict__ Qhi, __half* __restrict__ Qlo,
         __half* __restrict__ Kf, __half* __restrict__ Vf)
{
    extern __shared__ char smem[];
    const uint32_t sbase = smem_u32(smem);
    const int tid  = threadIdx.x;
    const int wid  = tid >> 5;
    const int lane = tid & 31;
    const int g    = lane >> 3;
    const int li   = lane & 7;
    const int warp_m = wid & 3;
    const int warp_n = wid >> 2;
    const int m0 = blockIdx.y * BM;
    const int n0 = blockIdx.x * BN;
    const int which = blockIdx.z;

    const __half* Bhi = Whi_all + (size_t)which * WSZ;
    const __half* Blo = Wlo_all + (size_t)which * WSZ;

    GEMM_MAINLOOP(Af, Bhi, Blo)

    const int b = m0 >> 11;
    const int ncol0 = n0 + warp_n * 32;
    const int h = ncol0 >> 6;
    const int dcol = (ncol0 & 63) + 2 * (lane & 3);
#pragma unroll
    for (int i = 0; i < 4; i++) {
        int r0 = m0 + warp_m * 64 + i * 16 + (lane >> 2);
        int r1 = r0 + 8;
        size_t d0 = (((size_t)b * NUM_HEADS + h) * S_ + (r0 & (S_ - 1))) * DK + dcol;
        size_t d1 = (((size_t)b * NUM_HEADS + h) * S_ + (r1 & (S_ - 1))) * DK + dcol;
        if (which == 0) {
#pragma unroll
            for (int j = 0; j < 4; j++) {
                uint32_t hv, lv;
                pack_hl_f16(acc[i][j][0], acc[i][j][1], hv, lv);
                *(uint32_t*)(Qhi + d0 + 8 * j) = hv;
                *(uint32_t*)(Qlo + d0 + 8 * j) = lv;
                pack_hl_f16(acc[i][j][2], acc[i][j][3], hv, lv);
                *(uint32_t*)(Qhi + d1 + 8 * j) = hv;
                *(uint32_t*)(Qlo + d1 + 8 * j) = lv;
            }
        } else {
            __half* C = (which == 1) ? Kf : Vf;
#pragma unroll
            for (int j = 0; j < 4; j++) {
                *(uint32_t*)(C + d0 + 8 * j) = pack_f16(acc[i][j][0], acc[i][j][1]);
                *(uint32_t*)(C + d1 + 8 * j) = pack_f16(acc[i][j][2], acc[i][j][3]);
            }
        }
    }
}

// --------------------------------------------------------------------------
// O-projection: fp32 output; grid (8, 16)
// --------------------------------------------------------------------------
__global__ void __launch_bounds__(512, 1)
gemm_out(const __half* __restrict__ Af, const __half* __restrict__ Bhi,
         const __half* __restrict__ Blo, float* __restrict__ C)
{
    extern __shared__ char smem[];
    const uint32_t sbase = smem_u32(smem);
    const int tid  = threadIdx.x;
    const int wid  = tid >> 5;
    const int lane = tid & 31;
    const int g    = lane >> 3;
    const int li   = lane & 7;
    const int warp_m = wid & 3;
    const int warp_n = wid >> 2;
    const int m0 = blockIdx.y * BM;
    const int n0 = blockIdx.x * BN;

    GEMM_MAINLOOP(Af, Bhi, Blo)

    const int ncol = n0 + warp_n * 32 + 2 * (lane & 3);
#pragma unroll
    for (int i = 0; i < 4; i++) {
        int r0 = m0 + warp_m * 64 + i * 16 + (lane >> 2);
        float* p0 = C + (size_t)r0 * D_MODEL + ncol;
        float* p1 = p0 + 8 * D_MODEL;
#pragma unroll
        for (int j = 0; j < 4; j++) {
            *(float2*)(p0 + 8 * j) = make_float2(acc[i][j][0], acc[i][j][1]);
            *(float2*)(p1 + 8 * j) = make_float2(acc[i][j][2], acc[i][j][3]);
        }
    }
}

// ===========================================================================
// Register-resident FA2, fp16x2 (unchanged from R14)
// ===========================================================================
#define QROWS 128
#define KTILE 64
#define PITCH 144
#define Q_BYTES (QROWS * PITCH)
#define KV_MAT (KTILE * PITCH)
#define KV_STG (2 * KV_MAT)
#define AT_Q 0
#define AT_KV (2 * Q_BYTES)
#define SMEM_ATTN (AT_KV + 2 * KV_STG)  // 73728

__global__ void __launch_bounds__(256)
attn_mma(const __half* __restrict__ Qhi_g, const __half* __restrict__ Qlo_g,
         const __half* __restrict__ Kf_g, const __half* __restrict__ Vf_g,
         __half* __restrict__ Af_g)
{
    extern __shared__ char smem[];
    const uint32_t sbase = smem_u32(smem);
    const int tid  = threadIdx.x;
    const int wid  = tid >> 5;
    const int lane = tid & 31;
    const int g    = lane >> 3;
    const int li   = lane & 7;

    const int bh = blockIdx.y;
    const int b  = bh >> 4;
    const int h  = bh & 15;
    const size_t hb = (size_t)bh * S_ * DK;

    const int qt = gridDim.x - 1 - blockIdx.x;
    const int q0 = qt * QROWS;
    const int wm = wid * 16;
    const int wrmax = q0 + wm + 15;

#pragma unroll
    for (int u = 0; u < 8; u++) {
        int idx = u * 256 + tid;
        int mat = idx >> 10;
        int wi  = idx & 1023;
        int r   = wi >> 3;
        int c8  = wi & 7;
        const __half* src = (mat == 0 ? Qhi_g : Qlo_g) + hb + (size_t)(q0 + r) * DK + c8 * 8;
        cp_async16(sbase + AT_Q + mat * Q_BYTES + r * PITCH + c8 * 16, src);
    }
    cp_async_commit();

    auto load_kv = [&](int kt, int s) {
        const int k0 = kt * KTILE;
        const uint32_t st = sbase + AT_KV + s * KV_STG;
#pragma unroll
        for (int u = 0; u < 4; u++) {
            int idx = u * 256 + tid;
            int mat = idx >> 9;
            int wi  = idx & 511;
            int r   = wi >> 3;
            int c8  = wi & 7;
            const __half* base = (mat == 0) ? Kf_g : Vf_g;
            cp_async16(st + mat * KV_MAT + r * PITCH + c8 * 16,
                       base + hb + (size_t)(k0 + r) * DK + c8 * 8);
        }
        cp_async_commit();
    };

    load_kv(0, 0);
    cp_async_wait<0>();
    __syncthreads();

    uint32_t qh[4][4], ql[4][4];
    {
        const uint32_t rowb = sbase + AT_Q + (uint32_t)(wm + ((g & 1) << 3) + li) * PITCH
                              + ((uint32_t)(g >> 1) << 4);
#pragma unroll
        for (int ks = 0; ks < 4; ks++) {
            ldsm_x4(qh[ks], rowb + ks * 32);
            ldsm_x4(ql[ks], rowb + ks * 32 + Q_BYTES);
        }
    }

    float Oc[8][4];
#pragma unroll
    for (int j = 0; j < 8; j++)
#pragma unroll
        for (int e = 0; e < 4; e++) Oc[j][e] = 0.f;
    float m0v = -1e30f, m1v = -1e30f, l0v = 0.f, l1v = 0.f;

    const int r0g = q0 + wm + (lane >> 2);
    const int r1g = r0g + 8;
    const int nkt = 2 * qt + 2;

    for (int kt = 0; kt < nkt; kt++) {
        const int s  = kt & 1;
        const int k0 = kt * KTILE;
        if (kt + 1 < nkt) load_kv(kt + 1, s ^ 1);
        if (kt + 1 < nkt) cp_async_wait<1>(); else cp_async_wait<0>();
        __syncthreads();

        if (k0 <= wrmax) {
            const uint32_t kb = sbase + AT_KV + s * KV_STG;

            float Sc[8][4];
#pragma unroll
            for (int j = 0; j < 8; j++)
#pragma unroll
                for (int e = 0; e < 4; e++) Sc[j][e] = 0.f;

#pragma unroll
            for (int ks = 0; ks < 4; ks++) {
#pragma unroll
                for (int jp = 0; jp < 4; jp++) {
                    uint32_t k4[4];
                    uint32_t addr = kb + (uint32_t)(jp * 16 + ((g >> 1) << 3) + li) * PITCH
                                    + ks * 32 + ((uint32_t)(g & 1) << 4);
                    ldsm_x4(k4, addr);
                    mma16816f(Sc[2 * jp],     qh[ks], k4 + 0);
                    mma16816f(Sc[2 * jp],     ql[ks], k4 + 0);
                    mma16816f(Sc[2 * jp + 1], qh[ks], k4 + 2);
                    mma16816f(Sc[2 * jp + 1], ql[ks], k4 + 2);
                }
            }

            float rx0 = -1e30f, rx1 = -1e30f;
#pragma unroll
            for (int j = 0; j < 8; j++) {
                int cb = k0 + 8 * j + 2 * (lane & 3);
#pragma unroll
                for (int e = 0; e < 2; e++) {
                    float v0 = Sc[j][e] * 0.125f;
                    float v1 = Sc[j][2 + e] * 0.125f;
                    if (cb + e > r0g) v0 = -1e30f;
                    if (cb + e > r1g) v1 = -1e30f;
                    Sc[j][e] = v0; Sc[j][2 + e] = v1;
                    rx0 = fmaxf(rx0, v0); rx1 = fmaxf(rx1, v1);
                }
            }
            rx0 = fmaxf(rx0, __shfl_xor_sync(0xffffffffu, rx0, 1, 4));
            rx0 = fmaxf(rx0, __shfl_xor_sync(0xffffffffu, rx0, 2, 4));
            rx1 = fmaxf(rx1, __shfl_xor_sync(0xffffffffu, rx1, 1, 4));
            rx1 = fmaxf(rx1, __shfl_xor_sync(0xffffffffu, rx1, 2, 4));

            float nm0 = fmaxf(m0v, rx0), nm1 = fmaxf(m1v, rx1);
            float cr0 = __expf(m0v - nm0), cr1 = __expf(m1v - nm1);
            float s0 = 0.f, s1 = 0.f;
#pragma unroll
            for (int j = 0; j < 8; j++) {
#pragma unroll
                for (int e = 0; e < 2; e++) {
                    float p0 = __expf(Sc[j][e] - nm0);
                    float p1 = __expf(Sc[j][2 + e] - nm1);
                    Sc[j][e] = p0; Sc[j][2 + e] = p1;
                    s0 += p0; s1 += p1;
                }
            }
            s0 += __shfl_xor_sync(0xffffffffu, s0, 1, 4);
            s0 += __shfl_xor_sync(0xffffffffu, s0, 2, 4);
            s1 += __shfl_xor_sync(0xffffffffu, s1, 1, 4);
            s1 += __shfl_xor_sync(0xffffffffu, s1, 2, 4);
            l0v = l0v * cr0 + s0;  l1v = l1v * cr1 + s1;
            m0v = nm0;  m1v = nm1;
#pragma unroll
            for (int j = 0; j < 8; j++) {
                Oc[j][0] *= cr0; Oc[j][1] *= cr0;
                Oc[j][2] *= cr1; Oc[j][3] *= cr1;
            }

            uint32_t ph[4][4], pl[4][4];
#pragma unroll
            for (int ks = 0; ks < 4; ks++) {
                int j0 = 2 * ks, j1 = 2 * ks + 1;
                pack_hl_f16(Sc[j0][0], Sc[j0][1], ph[ks][0], pl[ks][0]);
                pack_hl_f16(Sc[j0][2], Sc[j0][3], ph[ks][1], pl[ks][1]);
                pack_hl_f16(Sc[j1][0], Sc[j1][1], ph[ks][2], pl[ks][2]);
                pack_hl_f16(Sc[j1][2], Sc[j1][3], ph[ks][3], pl[ks][3]);
            }

            const uint32_t vb = kb + KV_MAT;
#pragma unroll
            for (int ks = 0; ks < 4; ks++) {
#pragma unroll
                for (int jp = 0; jp < 4; jp++) {
                    uint32_t v4[4];
                    uint32_t addr = vb + (uint32_t)(ks * 16 + ((g & 1) << 3) + li) * PITCH
                                    + jp * 32 + ((uint32_t)(g >> 1) << 4);
                    ldsm_x4_t(v4, addr);
                    mma16816f(Oc[2 * jp],     ph[ks], v4 + 0);
                    mma16816f(Oc[2 * jp],     pl[ks], v4 + 0);
                    mma16816f(Oc[2 * jp + 1], ph[ks], v4 + 2);
                    mma16816f(Oc[2 * jp + 1], pl[ks], v4 + 2);
                }
            }
        }
        __syncthreads();
    }

    {
        float il0 = 1.f / l0v, il1 = 1.f / l1v;
        size_t base0 = ((size_t)b * S_ + r0g) * D_MODEL + h * DK + 2 * (lane & 3);
        size_t base1 = ((size_t)b * S_ + r1g) * D_MODEL + h * DK + 2 * (lane & 3);
#pragma unroll
        for (int j = 0; j < 8; j++) {
            *(uint32_t*)(Af_g + base0 + 8 * j) = pack_f16(Oc[j][0] * il0, Oc[j][1] * il0);
            *(uint32_t*)(Af_g + base1 + 8 * j) = pack_f16(Oc[j][2] * il1, Oc[j][3] * il1);
        }
    }
}

// ===========================================================================
// Launch
// ===========================================================================
extern "C" void kernel_launch(void* const* d_in, const int* in_sizes, int n_in,
                              void* d_out, int out_size)
{
    (void)in_sizes; (void)n_in; (void)out_size;
    const float* x  = (const float*)d_in[0];
    const float* Wq = (const float*)d_in[1];
    const float* Wk = (const float*)d_in[2];
    const float* Wv = (const float*)d_in[3];
    const float* Wo = (const float*)d_in[4];
    float* out = (float*)d_out;

    __half *pxf, *pWh, *pWl, *pAf, *pQh, *pQl, *pKf, *pVf;
    cudaGetSymbolAddress((void**)&pxf, g_xf);
    cudaGetSymbolAddress((void**)&pWh, g_Whi);
    cudaGetSymbolAddress((void**)&pWl, g_Wlo);
    cudaGetSymbolAddress((void**)&pAf, g_Af);
    cudaGetSymbolAddress((void**)&pQh, g_Qhi);
    cudaGetSymbolAddress((void**)&pQl, g_Qlo);
    cudaGetSymbolAddress((void**)&pKf, g_Kf);
    cudaGetSymbolAddress((void**)&pVf, g_Vf);

    cudaFuncSetAttribute(gemm_qkv, cudaFuncAttributeMaxDynamicSharedMemorySize, SMEM_G3);
    cudaFuncSetAttribute(gemm_out, cudaFuncAttributeMaxDynamicSharedMemorySize, SMEM_G3);
    cudaFuncSetAttribute(attn_mma, cudaFuncAttributeMaxDynamicSharedMemorySize, SMEM_ATTN);

    split_all<<<(NX4 + 4 * NW4) / 256, 256>>>(x, Wq, Wk, Wv, Wo, pxf, pWh, pWl);

    dim3 qkvgrid(D_MODEL / BN, M_ROWS / BM, 3);     // (8, 16, 3) = 384 CTAs
    gemm_qkv<<<qkvgrid, 512, SMEM_G3>>>(pxf, pWh, pWl, pQh, pQl, pKf, pVf);

    dim3 agrid(S_ / QROWS, B_ * NUM_HEADS);         // (16, 32)
    attn_mma<<<agrid, 256, SMEM_ATTN>>>(pQh, pQl, pKf, pVf, pAf);

    dim3 ogrid(D_MODEL / BN, M_ROWS / BM);          // (8, 16) = 128 CTAs
    gemm_out<<<ogrid, 512, SMEM_G3>>>(pAf, pWh + 3 * WSZ, pWl + 3 * WSZ, out);
}

// round 16
// speedup vs baseline: 1.1896x; 1.1896x over previous
#include <cuda_runtime.h>
#include <cuda_fp16.h>
#include <math.h>
#include <stdint.h>

// Problem constants
#define D_MODEL   1024
#define NUM_HEADS 16
#define DK        64
#define B_        2
#define S_        2048
#define M_ROWS    (B_ * S_)   // 4096
#define WSZ       ((size_t)D_MODEL * D_MODEL)

// ===========================================================================
// Scratch (__device__ globals, allocation-free) — fp16
// ===========================================================================
__device__ __align__(128) __half g_xf [(size_t)M_ROWS * D_MODEL];
__device__ __align__(128) __half g_Whi[4][WSZ];
__device__ __align__(128) __half g_Wlo[4][WSZ];
__device__ __align__(128) __half g_Af [(size_t)M_ROWS * D_MODEL];

__device__ __align__(128) __half g_Qhi[(size_t)M_ROWS * D_MODEL];   // pre-scaled by 0.125
__device__ __align__(128) __half g_Qlo[(size_t)M_ROWS * D_MODEL];
__device__ __align__(128) __half g_Kf [(size_t)M_ROWS * D_MODEL];
__device__ __align__(128) __half g_Vf [(size_t)M_ROWS * D_MODEL];

// ===========================================================================
// helpers
// ===========================================================================
__device__ __forceinline__ uint32_t smem_u32(const void* p) {
    uint32_t a;
    asm("{ .reg .u64 t; cvta.to.shared.u64 t, %1; cvt.u32.u64 %0, t; }"
        : "=r"(a) : "l"(p));
    return a;
}
__device__ __forceinline__ void cp_async16(uint32_t dst, const void* src) {
    uint64_t gsrc = __cvta_generic_to_global(src);
    asm volatile("cp.async.cg.shared.global [%0], [%1], 16;" :: "r"(dst), "l"(gsrc));
}
__device__ __forceinline__ void cp_async_commit() {
    asm volatile("cp.async.commit_group;" ::: "memory");
}
template <int N>
__device__ __forceinline__ void cp_async_wait() {
    asm volatile("cp.async.wait_group %0;" :: "n"(N) : "memory");
}
__device__ __forceinline__ void ldsm_x4(uint32_t r[4], uint32_t addr) {
    asm volatile("ldmatrix.sync.aligned.m8n8.x4.shared.b16 {%0,%1,%2,%3}, [%4];"
                 : "=r"(r[0]), "=r"(r[1]), "=r"(r[2]), "=r"(r[3]) : "r"(addr));
}
__device__ __forceinline__ void ldsm_x4_t(uint32_t r[4], uint32_t addr) {
    asm volatile("ldmatrix.sync.aligned.m8n8.x4.trans.shared.b16 {%0,%1,%2,%3}, [%4];"
                 : "=r"(r[0]), "=r"(r[1]), "=r"(r[2]), "=r"(r[3]) : "r"(addr));
}
__device__ __forceinline__ void mma16816f(float c[4], const uint32_t a[4], const uint32_t b[2]) {
    asm volatile("mma.sync.aligned.m16n8k16.row.col.f32.f16.f16.f32 "
                 "{%0,%1,%2,%3}, {%4,%5,%6,%7}, {%8,%9}, {%0,%1,%2,%3};"
                 : "+f"(c[0]), "+f"(c[1]), "+f"(c[2]), "+f"(c[3])
                 : "r"(a[0]), "r"(a[1]), "r"(a[2]), "r"(a[3]), "r"(b[0]), "r"(b[1]));
}
__device__ __forceinline__ uint32_t pack_f16(float x, float y) {
    __half2 h = __float22half2_rn(make_float2(x, y));
    return *reinterpret_cast<uint32_t*>(&h);
}
__device__ __forceinline__ void pack_hl_f16(float x, float y, uint32_t& hv, uint32_t& lv) {
    __half2 h = __float22half2_rn(make_float2(x, y));
    float2 hf = __half22float2(h);
    __half2 l = __float22half2_rn(make_float2(x - hf.x, y - hf.y));
    hv = *reinterpret_cast<uint32_t*>(&h);
    lv = *reinterpret_cast<uint32_t*>(&l);
}

// ===========================================================================
// merged fp32 -> fp16 split for x (single) + 4 weights (hi/lo), one launch
// ===========================================================================
#define NX4 (1 << 20)
#define NW4 (1 << 18)

__global__ __launch_bounds__(256)
void split_all(const float* __restrict__ x,
               const float* __restrict__ Wq, const float* __restrict__ Wk,
               const float* __restrict__ Wv, const float* __restrict__ Wo,
               __half* __restrict__ xf,
               __half* __restrict__ Whi, __half* __restrict__ Wlo)
{
    int i = blockIdx.x * 256 + threadIdx.x;
    if (i < NX4) {
        float4 v = ((const float4*)x)[i];
        ((uint32_t*)xf)[i * 2 + 0] = pack_f16(v.x, v.y);
        ((uint32_t*)xf)[i * 2 + 1] = pack_f16(v.z, v.w);
    } else {
        int j = i - NX4;
        int w = j >> 18;
        int idx = j & (NW4 - 1);
        const float* in = (w == 0) ? Wq : (w == 1) ? Wk : (w == 2) ? Wv : Wo;
        __half* hi = Whi + (size_t)w * WSZ;
        __half* lo = Wlo + (size_t)w * WSZ;
        float4 v = ((const float4*)in)[idx];
        uint32_t h01, l01, h23, l23;
        pack_hl_f16(v.x, v.y, h01, l01);
        pack_hl_f16(v.z, v.w, h23, l23);
        ((uint32_t*)hi)[idx * 2 + 0] = h01;
        ((uint32_t*)hi)[idx * 2 + 1] = h23;
        ((uint32_t*)lo)[idx * 2 + 0] = l01;
        ((uint32_t*)lo)[idx * 2 + 1] = l23;
    }
}

// ===========================================================================
// Raw mma.sync fp16x2 GEMM — block 256x128, 512 thr (16 warps, 4m x 4n),
// warp tile 64x32, BK=32, 3-stage cp.async, ONE barrier per chunk.
// Both passes f32 accumulate (R14 configuration).
// ===========================================================================
#define BM 256
#define BN 128
#define BK 32
#define GP 80
#define A_MAT (BM * GP)                 // 20480
#define B_MAT (BN * GP)                 // 10240
#define STG_BYTES (A_MAT + 2 * B_MAT)   // 40960
#define OFF_B A_MAT
#define SMEM_G3 (3 * STG_BYTES)         // 122880
#define NSTGK (D_MODEL / BK)            // 32

#define GEMM_MAINLOOP(Af_, Bhi_, Blo_)                                          \
    float acc[4][4][4];                                                         \
    _Pragma("unroll") for (int i = 0; i < 4; i++)                               \
        _Pragma("unroll") for (int j = 0; j < 4; j++)                           \
            _Pragma("unroll") for (int e = 0; e < 4; e++) acc[i][j][e] = 0.f;   \
    auto load_stage = [&](int c, int s) {                                       \
        const int k0 = c * BK;                                                  \
        const uint32_t st = sbase + s * STG_BYTES;                              \
        _Pragma("unroll") for (int u = 0; u < 2; u++) {                         \
            int wi = tid + u * 512;                                             \
            int r  = wi >> 2;                                                   \
            int c8 = wi & 3;                                                    \
            size_t ga = (size_t)(m0 + r) * D_MODEL + k0 + c8 * 8;               \
            cp_async16(st + (uint32_t)(r * GP + c8 * 16), (Af_) + ga);          \
        }                                                                       \
        _Pragma("unroll") for (int u = 0; u < 2; u++) {                         \
            int idx = tid + u * 512;                                            \
            int mat = idx >> 9;                                                 \
            int wi  = idx & 511;                                                \
            int r   = wi >> 2;                                                  \
            int c8  = wi & 3;                                                   \
            size_t gb = (size_t)(n0 + r) * D_MODEL + k0 + c8 * 8;               \
            cp_async16(st + OFF_B + mat * B_MAT + (uint32_t)(r * GP + c8 * 16), \
                       (mat == 0 ? (Bhi_) : (Blo_)) + gb);                      \
        }                                                                       \
        cp_async_commit();                                                      \
    };                                                                          \
    load_stage(0, 0);                                                           \
    load_stage(1, 1);                                                           \
    for (int c = 0; c < NSTGK; c++) {                                           \
        const int s = c % 3;                                                    \
        if (c + 1 < NSTGK) cp_async_wait<1>(); else cp_async_wait<0>();         \
        __syncthreads();                                                        \
        if (c + 2 < NSTGK) load_stage(c + 2, (c + 2) % 3);                      \
        const uint32_t aB = sbase + s * STG_BYTES;                              \
        const uint32_t bB = aB + OFF_B;                                         \
        _Pragma("unroll") for (int ks = 0; ks < 2; ks++) {                      \
            uint32_t af[4][4];                                                  \
            _Pragma("unroll") for (int i = 0; i < 4; i++) {                     \
                uint32_t ar = aB + (uint32_t)(warp_m * 64 + i * 16              \
                               + ((g & 1) << 3) + li) * GP                      \
                               + ks * 32 + ((uint32_t)(g >> 1) << 4);           \
                ldsm_x4(af[i], ar);                                             \
            }                                                                   \
            _Pragma("unroll") for (int j4 = 0; j4 < 2; j4++) {                  \
                uint32_t bh4[4], bl4[4];                                        \
                uint32_t br = bB + (uint32_t)(warp_n * 32 + j4 * 16             \
                               + ((g >> 1) << 3) + li) * GP                     \
                               + ks * 32 + ((uint32_t)(g & 1) << 4);            \
                ldsm_x4(bh4, br);                                               \
                ldsm_x4(bl4, br + B_MAT);                                       \
                _Pragma("unroll") for (int i = 0; i < 4; i++) {                 \
                    mma16816f(acc[i][2 * j4],     af[i], bh4 + 0);              \
                    mma16816f(acc[i][2 * j4],     af[i], bl4 + 0);              \
                    mma16816f(acc[i][2 * j4 + 1], af[i], bh4 + 2);              \
                    mma16816f(acc[i][2 * j4 + 1], af[i], bl4 + 2);              \
                }                                                               \
            }                                                                   \
        }                                                                       \
    }

// --------------------------------------------------------------------------
// fused QKV projection: grid (8, 16, 3)
// which==0 -> Q hi/lo (pre-scaled by 0.125); 1 -> K single; 2 -> V single
// --------------------------------------------------------------------------
__global__ void __launch_bounds__(512, 1)
gemm_qkv(const __half* __restrict__ Af, const __half* __restrict__ Whi_all,
         const __half* __restrict__ Wlo_all,
         __half* __restrict__ Qhi, __half* __restrict__ Qlo,
         __half* __restrict__ Kf, __half* __restrict__ Vf)
{
    extern __shared__ char smem[];
    const uint32_t sbase = smem_u32(smem);
    const int tid  = threadIdx.x;
    const int wid  = tid >> 5;
    const int lane = tid & 31;
    const int g    = lane >> 3;
    const int li   = lane & 7;
    const int warp_m = wid & 3;
    const int warp_n = wid >> 2;
    const int m0 = blockIdx.y * BM;
    const int n0 = blockIdx.x * BN;
    const int which = blockIdx.z;

    const __half* Bhi = Whi_all + (size_t)which * WSZ;
    const __half* Blo = Wlo_all + (size_t)which * WSZ;

    GEMM_MAINLOOP(Af, Bhi, Blo)

    const int b = m0 >> 11;
    const int ncol0 = n0 + warp_n * 32;
    const int h = ncol0 >> 6;
    const int dcol = (ncol0 & 63) + 2 * (lane & 3);
#pragma unroll
    for (int i = 0; i < 4; i++) {
        int r0 = m0 + warp_m * 64 + i * 16 + (lane >> 2);
        int r1 = r0 + 8;
        size_t d0 = (((size_t)b * NUM_HEADS + h) * S_ + (r0 & (S_ - 1))) * DK + dcol;
        size_t d1 = (((size_t)b * NUM_HEADS + h) * S_ + (r1 & (S_ - 1))) * DK + dcol;
        if (which == 0) {
#pragma unroll
            for (int j = 0; j < 4; j++) {
                uint32_t hv, lv;
                pack_hl_f16(acc[i][j][0] * 0.125f, acc[i][j][1] * 0.125f, hv, lv);
                *(uint32_t*)(Qhi + d0 + 8 * j) = hv;
                *(uint32_t*)(Qlo + d0 + 8 * j) = lv;
                pack_hl_f16(acc[i][j][2] * 0.125f, acc[i][j][3] * 0.125f, hv, lv);
                *(uint32_t*)(Qhi + d1 + 8 * j) = hv;
                *(uint32_t*)(Qlo + d1 + 8 * j) = lv;
            }
        } else {
            __half* C = (which == 1) ? Kf : Vf;
#pragma unroll
            for (int j = 0; j < 4; j++) {
                *(uint32_t*)(C + d0 + 8 * j) = pack_f16(acc[i][j][0], acc[i][j][1]);
                *(uint32_t*)(C + d1 + 8 * j) = pack_f16(acc[i][j][2], acc[i][j][3]);
            }
        }
    }
}

// --------------------------------------------------------------------------
// O-projection: fp32 output; grid (8, 16)
// --------------------------------------------------------------------------
__global__ void __launch_bounds__(512, 1)
gemm_out(const __half* __restrict__ Af, const __half* __restrict__ Bhi,
         const __half* __restrict__ Blo, float* __restrict__ C)
{
    extern __shared__ char smem[];
    const uint32_t sbase = smem_u32(smem);
    const int tid  = threadIdx.x;
    const int wid  = tid >> 5;
    const int lane = tid & 31;
    const int g    = lane >> 3;
    const int li   = lane & 7;
    const int warp_m = wid & 3;
    const int warp_n = wid >> 2;
    const int m0 = blockIdx.y * BM;
    const int n0 = blockIdx.x * BN;

    GEMM_MAINLOOP(Af, Bhi, Blo)

    const int ncol = n0 + warp_n * 32 + 2 * (lane & 3);
#pragma unroll
    for (int i = 0; i < 4; i++) {
        int r0 = m0 + warp_m * 64 + i * 16 + (lane >> 2);
        float* p0 = C + (size_t)r0 * D_MODEL + ncol;
        float* p1 = p0 + 8 * D_MODEL;
#pragma unroll
        for (int j = 0; j < 4; j++) {
            *(float2*)(p0 + 8 * j) = make_float2(acc[i][j][0], acc[i][j][1]);
            *(float2*)(p1 + 8 * j) = make_float2(acc[i][j][2], acc[i][j][3]);
        }
    }
}

// ===========================================================================
// Register-resident FA2, fp16x2, 3-stage KV pipeline.
// Q pre-scaled by 0.125 (no scale in softmax loop).
// ===========================================================================
#define QROWS 128
#define KTILE 64
#define PITCH 144
#define Q_BYTES (QROWS * PITCH)
#define KV_MAT (KTILE * PITCH)
#define KV_STG (2 * KV_MAT)             // 18432: K + V single
#define AT_Q 0
#define AT_KV (2 * Q_BYTES)             // 36864
#define SMEM_ATTN (AT_KV + 3 * KV_STG)  // 92160

__global__ void __launch_bounds__(256)
attn_mma(const __half* __restrict__ Qhi_g, const __half* __restrict__ Qlo_g,
         const __half* __restrict__ Kf_g, const __half* __restrict__ Vf_g,
         __half* __restrict__ Af_g)
{
    extern __shared__ char smem[];
    const uint32_t sbase = smem_u32(smem);
    const int tid  = threadIdx.x;
    const int wid  = tid >> 5;
    const int lane = tid & 31;
    const int g    = lane >> 3;
    const int li   = lane & 7;

    const int bh = blockIdx.y;
    const int b  = bh >> 4;
    const int h  = bh & 15;
    const size_t hb = (size_t)bh * S_ * DK;

    const int qt = gridDim.x - 1 - blockIdx.x;
    const int q0 = qt * QROWS;
    const int wm = wid * 16;
    const int wrmax = q0 + wm + 15;

    // Q hi/lo -> smem
#pragma unroll
    for (int u = 0; u < 8; u++) {
        int idx = u * 256 + tid;
        int mat = idx >> 10;
        int wi  = idx & 1023;
        int r   = wi >> 3;
        int c8  = wi & 7;
        const __half* src = (mat == 0 ? Qhi_g : Qlo_g) + hb + (size_t)(q0 + r) * DK + c8 * 8;
        cp_async16(sbase + AT_Q + mat * Q_BYTES + r * PITCH + c8 * 16, src);
    }
    cp_async_commit();

    auto load_kv = [&](int kt, int s) {
        const int k0 = kt * KTILE;
        const uint32_t st = sbase + AT_KV + s * KV_STG;
#pragma unroll
        for (int u = 0; u < 4; u++) {
            int idx = u * 256 + tid;
            int mat = idx >> 9;
            int wi  = idx & 511;
            int r   = wi >> 3;
            int c8  = wi & 7;
            const __half* base = (mat == 0) ? Kf_g : Vf_g;
            cp_async16(st + mat * KV_MAT + r * PITCH + c8 * 16,
                       base + hb + (size_t)(k0 + r) * DK + c8 * 8);
        }
        cp_async_commit();
    };

    const int nkt = 2 * qt + 2;
    load_kv(0, 0);
    if (1 < nkt) load_kv(1, 1);
    if (1 < nkt) cp_async_wait<1>(); else cp_async_wait<0>();  // Q + kv0 done
    __syncthreads();

    uint32_t qh[4][4], ql[4][4];
    {
        const uint32_t rowb = sbase + AT_Q + (uint32_t)(wm + ((g & 1) << 3) + li) * PITCH
                              + ((uint32_t)(g >> 1) << 4);
#pragma unroll
        for (int ks = 0; ks < 4; ks++) {
            ldsm_x4(qh[ks], rowb + ks * 32);
            ldsm_x4(ql[ks], rowb + ks * 32 + Q_BYTES);
        }
    }

    float Oc[8][4];
#pragma unroll
    for (int j = 0; j < 8; j++)
#pragma unroll
        for (int e = 0; e < 4; e++) Oc[j][e] = 0.f;
    float m0v = -1e30f, m1v = -1e30f, l0v = 0.f, l1v = 0.f;

    const int r0g = q0 + wm + (lane >> 2);
    const int r1g = r0g + 8;

    for (int kt = 0; kt < nkt; kt++) {
        const int s  = kt % 3;
        const int k0 = kt * KTILE;
        // wait for kv(kt); pending beyond it: at most kv(kt+1)
        if (kt + 1 < nkt) cp_async_wait<1>(); else cp_async_wait<0>();
        __syncthreads();   // all warps finished reading slot (kt+2)%3 (iter kt-1)
        if (kt + 2 < nkt) load_kv(kt + 2, (kt + 2) % 3);

        if (k0 <= wrmax) {
            const uint32_t kb = sbase + AT_KV + s * KV_STG;

            // ---- S = (Qhi + Qlo) K^T  (Q pre-scaled) ----
            float Sc[8][4];
#pragma unroll
            for (int j = 0; j < 8; j++)
#pragma unroll
                for (int e = 0; e < 4; e++) Sc[j][e] = 0.f;

#pragma unroll
            for (int ks = 0; ks < 4; ks++) {
#pragma unroll
                for (int jp = 0; jp < 4; jp++) {
                    uint32_t k4[4];
                    uint32_t addr = kb + (uint32_t)(jp * 16 + ((g >> 1) << 3) + li) * PITCH
                                    + ks * 32 + ((uint32_t)(g & 1) << 4);
                    ldsm_x4(k4, addr);
                    mma16816f(Sc[2 * jp],     qh[ks], k4 + 0);
                    mma16816f(Sc[2 * jp],     ql[ks], k4 + 0);
                    mma16816f(Sc[2 * jp + 1], qh[ks], k4 + 2);
                    mma16816f(Sc[2 * jp + 1], ql[ks], k4 + 2);
                }
            }

            // ---- softmax in registers ----
            float rx0 = -1e30f, rx1 = -1e30f;
#pragma unroll
            for (int j = 0; j < 8; j++) {
                int cb = k0 + 8 * j + 2 * (lane & 3);
#pragma unroll
                for (int e = 0; e < 2; e++) {
                    float v0 = Sc[j][e];
                    float v1 = Sc[j][2 + e];
                    if (cb + e > r0g) v0 = -1e30f;
                    if (cb + e > r1g) v1 = -1e30f;
                    Sc[j][e] = v0; Sc[j][2 + e] = v1;
                    rx0 = fmaxf(rx0, v0); rx1 = fmaxf(rx1, v1);
                }
            }
            rx0 = fmaxf(rx0, __shfl_xor_sync(0xffffffffu, rx0, 1, 4));
            rx0 = fmaxf(rx0, __shfl_xor_sync(0xffffffffu, rx0, 2, 4));
            rx1 = fmaxf(rx1, __shfl_xor_sync(0xffffffffu, rx1, 1, 4));
            rx1 = fmaxf(rx1, __shfl_xor_sync(0xffffffffu, rx1, 2, 4));

            float nm0 = fmaxf(m0v, rx0), nm1 = fmaxf(m1v, rx1);
            float cr0 = __expf(m0v - nm0), cr1 = __expf(m1v - nm1);
            float s0 = 0.f, s1 = 0.f;
#pragma unroll
            for (int j = 0; j < 8; j++) {
#pragma unroll
                for (int e = 0; e < 2; e++) {
                    float p0 = __expf(Sc[j][e] - nm0);
                    float p1 = __expf(Sc[j][2 + e] - nm1);
                    Sc[j][e] = p0; Sc[j][2 + e] = p1;
                    s0 += p0; s1 += p1;
                }
            }
            s0 += __shfl_xor_sync(0xffffffffu, s0, 1, 4);
            s0 += __shfl_xor_sync(0xffffffffu, s0, 2, 4);
            s1 += __shfl_xor_sync(0xffffffffu, s1, 1, 4);
            s1 += __shfl_xor_sync(0xffffffffu, s1, 2, 4);
            l0v = l0v * cr0 + s0;  l1v = l1v * cr1 + s1;
            m0v = nm0;  m1v = nm1;
#pragma unroll
            for (int j = 0; j < 8; j++) {
                Oc[j][0] *= cr0; Oc[j][1] *= cr0;
                Oc[j][2] *= cr1; Oc[j][3] *= cr1;
            }

            // ---- P -> fp16 hi/lo A-fragments ----
            uint32_t ph[4][4], pl[4][4];
#pragma unroll
            for (int ks = 0; ks < 4; ks++) {
                int j0 = 2 * ks, j1 = 2 * ks + 1;
                pack_hl_f16(Sc[j0][0], Sc[j0][1], ph[ks][0], pl[ks][0]);
                pack_hl_f16(Sc[j0][2], Sc[j0][3], ph[ks][1], pl[ks][1]);
                pack_hl_f16(Sc[j1][0], Sc[j1][1], ph[ks][2], pl[ks][2]);
                pack_hl_f16(Sc[j1][2], Sc[j1][3], ph[ks][3], pl[ks][3]);
            }

            // ---- O += (Phi + Plo) V ----
            const uint32_t vb = kb + KV_MAT;
#pragma unroll
            for (int ks = 0; ks < 4; ks++) {
#pragma unroll
                for (int jp = 0; jp < 4; jp++) {
                    uint32_t v4[4];
                    uint32_t addr = vb + (uint32_t)(ks * 16 + ((g & 1) << 3) + li) * PITCH
                                    + jp * 32 + ((uint32_t)(g >> 1) << 4);
                    ldsm_x4_t(v4, addr);
                    mma16816f(Oc[2 * jp],     ph[ks], v4 + 0);
                    mma16816f(Oc[2 * jp],     pl[ks], v4 + 0);
                    mma16816f(Oc[2 * jp + 1], ph[ks], v4 + 2);
                    mma16816f(Oc[2 * jp + 1], pl[ks], v4 + 2);
                }
            }
        }
    }
    __syncthreads();

    // epilogue: normalize, single-fp16 store to A [B,S,D]
    {
        float il0 = 1.f / l0v, il1 = 1.f / l1v;
        size_t base0 = ((size_t)b * S_ + r0g) * D_MODEL + h * DK + 2 * (lane & 3);
        size_t base1 = ((size_t)b * S_ + r1g) * D_MODEL + h * DK + 2 * (lane & 3);
#pragma unroll
        for (int j = 0; j < 8; j++) {
            *(uint32_t*)(Af_g + base0 + 8 * j) = pack_f16(Oc[j][0] * il0, Oc[j][1] * il0);
            *(uint32_t*)(Af_g + base1 + 8 * j) = pack_f16(Oc[j][2] * il1, Oc[j][3] * il1);
        }
    }
}

// ===========================================================================
// Launch
// ===========================================================================
extern "C" void kernel_launch(void* const* d_in, const int* in_sizes, int n_in,
                              void* d_out, int out_size)
{
    (void)in_sizes; (void)n_in; (void)out_size;
    const float* x  = (const float*)d_in[0];
    const float* Wq = (const float*)d_in[1];
    const float* Wk = (const float*)d_in[2];
    const float* Wv = (const float*)d_in[3];
    const float* Wo = (const float*)d_in[4];
    float* out = (float*)d_out;

    __half *pxf, *pWh, *pWl, *pAf, *pQh, *pQl, *pKf, *pVf;
    cudaGetSymbolAddress((void**)&pxf, g_xf);
    cudaGetSymbolAddress((void**)&pWh, g_Whi);
    cudaGetSymbolAddress((void**)&pWl, g_Wlo);
    cudaGetSymbolAddress((void**)&pAf, g_Af);
    cudaGetSymbolAddress((void**)&pQh, g_Qhi);
    cudaGetSymbolAddress((void**)&pQl, g_Qlo);
    cudaGetSymbolAddress((void**)&pKf, g_Kf);
    cudaGetSymbolAddress((void**)&pVf, g_Vf);

    cudaFuncSetAttribute(gemm_qkv, cudaFuncAttributeMaxDynamicSharedMemorySize, SMEM_G3);
    cudaFuncSetAttribute(gemm_out, cudaFuncAttributeMaxDynamicSharedMemorySize, SMEM_G3);
    cudaFuncSetAttribute(attn_mma, cudaFuncAttributeMaxDynamicSharedMemorySize, SMEM_ATTN);

    split_all<<<(NX4 + 4 * NW4) / 256, 256>>>(x, Wq, Wk, Wv, Wo, pxf, pWh, pWl);

    dim3 qkvgrid(D_MODEL / BN, M_ROWS / BM, 3);     // (8, 16, 3) = 384 CTAs
    gemm_qkv<<<qkvgrid, 512, SMEM_G3>>>(pxf, pWh, pWl, pQh, pQl, pKf, pVf);

    dim3 agrid(S_ / QROWS, B_ * NUM_HEADS);         // (16, 32)
    attn_mma<<<agrid, 256, SMEM_ATTN>>>(pQh, pQl, pKf, pVf, pAf);

    dim3 ogrid(D_MODEL / BN, M_ROWS / BM);          // (8, 16) = 128 CTAs
    gemm_out<<<ogrid, 512, SMEM_G3>>>(pAf, pWh + 3 * WSZ, pWl + 3 * WSZ, out);
}

// round 17
// speedup vs baseline: 1.3019x; 1.0944x over previous
#include <cuda_runtime.h>
#include <cuda_fp16.h>
#include <math.h>
#include <stdint.h>

// Problem constants
#define D_MODEL   1024
#define NUM_HEADS 16
#define DK        64
#define B_        2
#define S_        2048
#define M_ROWS    (B_ * S_)   // 4096
#define WSZ       ((size_t)D_MODEL * D_MODEL)

// ===========================================================================
// Scratch (__device__ globals, allocation-free) — fp16
// ===========================================================================
__device__ __align__(128) __half g_xf [(size_t)M_ROWS * D_MODEL];
__device__ __align__(128) __half g_Whi[4][WSZ];
__device__ __align__(128) __half g_Wlo[4][WSZ];
__device__ __align__(128) __half g_Af [(size_t)M_ROWS * D_MODEL];

__device__ __align__(128) __half g_Qhi[(size_t)M_ROWS * D_MODEL];   // pre-scaled by 0.125
__device__ __align__(128) __half g_Qlo[(size_t)M_ROWS * D_MODEL];
__device__ __align__(128) __half g_Kf [(size_t)M_ROWS * D_MODEL];
__device__ __align__(128) __half g_Vf [(size_t)M_ROWS * D_MODEL];

// ===========================================================================
// helpers
// ===========================================================================
__device__ __forceinline__ uint32_t smem_u32(const void* p) {
    uint32_t a;
    asm("{ .reg .u64 t; cvta.to.shared.u64 t, %1; cvt.u32.u64 %0, t; }"
        : "=r"(a) : "l"(p));
    return a;
}
__device__ __forceinline__ void cp_async16(uint32_t dst, const void* src) {
    uint64_t gsrc = __cvta_generic_to_global(src);
    asm volatile("cp.async.cg.shared.global [%0], [%1], 16;" :: "r"(dst), "l"(gsrc));
}
__device__ __forceinline__ void cp_async_commit() {
    asm volatile("cp.async.commit_group;" ::: "memory");
}
template <int N>
__device__ __forceinline__ void cp_async_wait() {
    asm volatile("cp.async.wait_group %0;" :: "n"(N) : "memory");
}
__device__ __forceinline__ void ldsm_x4(uint32_t r[4], uint32_t addr) {
    asm volatile("ldmatrix.sync.aligned.m8n8.x4.shared.b16 {%0,%1,%2,%3}, [%4];"
                 : "=r"(r[0]), "=r"(r[1]), "=r"(r[2]), "=r"(r[3]) : "r"(addr));
}
__device__ __forceinline__ void ldsm_x4_t(uint32_t r[4], uint32_t addr) {
    asm volatile("ldmatrix.sync.aligned.m8n8.x4.trans.shared.b16 {%0,%1,%2,%3}, [%4];"
                 : "=r"(r[0]), "=r"(r[1]), "=r"(r[2]), "=r"(r[3]) : "r"(addr));
}
__device__ __forceinline__ void mma16816f(float c[4], const uint32_t a[4], const uint32_t b[2]) {
    asm volatile("mma.sync.aligned.m16n8k16.row.col.f32.f16.f16.f32 "
                 "{%0,%1,%2,%3}, {%4,%5,%6,%7}, {%8,%9}, {%0,%1,%2,%3};"
                 : "+f"(c[0]), "+f"(c[1]), "+f"(c[2]), "+f"(c[3])
                 : "r"(a[0]), "r"(a[1]), "r"(a[2]), "r"(a[3]), "r"(b[0]), "r"(b[1]));
}
__device__ __forceinline__ uint32_t pack_f16(float x, float y) {
    __half2 h = __float22half2_rn(make_float2(x, y));
    return *reinterpret_cast<uint32_t*>(&h);
}
__device__ __forceinline__ void pack_hl_f16(float x, float y, uint32_t& hv, uint32_t& lv) {
    __half2 h = __float22half2_rn(make_float2(x, y));
    float2 hf = __half22float2(h);
    __half2 l = __float22half2_rn(make_float2(x - hf.x, y - hf.y));
    hv = *reinterpret_cast<uint32_t*>(&h);
    lv = *reinterpret_cast<uint32_t*>(&l);
}

// ===========================================================================
// merged fp32 -> fp16 split for x (single) + 4 weights (hi/lo), one launch
// ===========================================================================
#define NX4 (1 << 20)
#define NW4 (1 << 18)

__global__ __launch_bounds__(256)
void split_all(const float* __restrict__ x,
               const float* __restrict__ Wq, const float* __restrict__ Wk,
               const float* __restrict__ Wv, const float* __restrict__ Wo,
               __half* __restrict__ xf,
               __half* __restrict__ Whi, __half* __restrict__ Wlo)
{
    int i = blockIdx.x * 256 + threadIdx.x;
    if (i < NX4) {
        float4 v = ((const float4*)x)[i];
        ((uint32_t*)xf)[i * 2 + 0] = pack_f16(v.x, v.y);
        ((uint32_t*)xf)[i * 2 + 1] = pack_f16(v.z, v.w);
    } else {
        int j = i - NX4;
        int w = j >> 18;
        int idx = j & (NW4 - 1);
        const float* in = (w == 0) ? Wq : (w == 1) ? Wk : (w == 2) ? Wv : Wo;
        __half* hi = Whi + (size_t)w * WSZ;
        __half* lo = Wlo + (size_t)w * WSZ;
        float4 v = ((const float4*)in)[idx];
        uint32_t h01, l01, h23, l23;
        pack_hl_f16(v.x, v.y, h01, l01);
        pack_hl_f16(v.z, v.w, h23, l23);
        ((uint32_t*)hi)[idx * 2 + 0] = h01;
        ((uint32_t*)hi)[idx * 2 + 1] = h23;
        ((uint32_t*)lo)[idx * 2 + 0] = l01;
        ((uint32_t*)lo)[idx * 2 + 1] = l23;
    }
}

// ===========================================================================
// Raw mma.sync fp16 GEMM — block 256x128, 512 thr (16 warps, 4m x 4n),
// warp tile 64x32, BK=32, 3-stage cp.async, ONE barrier per chunk.
// LOPASS (uniform bool) selects 2-pass (hi+lo weights) vs 1-pass (hi only).
// ===========================================================================
#define BM 256
#define BN 128
#define BK 32
#define GP 80
#define A_MAT (BM * GP)                 // 20480
#define B_MAT (BN * GP)                 // 10240
#define STG_BYTES (A_MAT + 2 * B_MAT)   // 40960
#define OFF_B A_MAT
#define SMEM_G3 (3 * STG_BYTES)         // 122880
#define NSTGK (D_MODEL / BK)            // 32

#define GEMM_MAINLOOP(Af_, Bhi_, Blo_, LOPASS_)                                 \
    float acc[4][4][4];                                                         \
    _Pragma("unroll") for (int i = 0; i < 4; i++)                               \
        _Pragma("unroll") for (int j = 0; j < 4; j++)                           \
            _Pragma("unroll") for (int e = 0; e < 4; e++) acc[i][j][e] = 0.f;   \
    auto load_stage = [&](int c, int s) {                                       \
        const int k0 = c * BK;                                                  \
        const uint32_t st = sbase + s * STG_BYTES;                              \
        _Pragma("unroll") for (int u = 0; u < 2; u++) {                         \
            int wi = tid + u * 512;                                             \
            int r  = wi >> 2;                                                   \
            int c8 = wi & 3;                                                    \
            size_t ga = (size_t)(m0 + r) * D_MODEL + k0 + c8 * 8;               \
            cp_async16(st + (uint32_t)(r * GP + c8 * 16), (Af_) + ga);          \
        }                                                                       \
        {                                                                       \
            int wi = tid & 511;                                                 \
            int mat = tid >> 9;                                                 \
            int r   = wi >> 2;                                                  \
            int c8  = wi & 3;                                                   \
            size_t gb = (size_t)(n0 + r) * D_MODEL + k0 + c8 * 8;               \
            if (mat == 0)                                                       \
                cp_async16(st + OFF_B + (uint32_t)(r * GP + c8 * 16),           \
                           (Bhi_) + gb);                                        \
            else if (LOPASS_)                                                   \
                cp_async16(st + OFF_B + B_MAT + (uint32_t)(r * GP + c8 * 16),   \
                           (Blo_) + gb);                                        \
        }                                                                       \
        {   /* second half of B rows */                                         \
            int idx = tid + 512;                                                \
            int wi  = idx & 511;                                                \
            int mat = (idx >> 9) & 1;                                           \
            int r   = wi >> 2;                                                  \
            int c8  = wi & 3;                                                   \
            size_t gb = (size_t)(n0 + r) * D_MODEL + k0 + c8 * 8;               \
            if (mat == 0)                                                       \
                cp_async16(st + OFF_B + (uint32_t)(r * GP + c8 * 16),           \
                           (Bhi_) + gb);                                        \
            else if (LOPASS_)                                                   \
                cp_async16(st + OFF_B + B_MAT + (uint32_t)(r * GP + c8 * 16),   \
                           (Blo_) + gb);                                        \
        }                                                                       \
        cp_async_commit();                                                      \
    };                                                                          \
    load_stage(0, 0);                                                           \
    load_stage(1, 1);                                                           \
    for (int c = 0; c < NSTGK; c++) {                                           \
        const int s = c % 3;                                                    \
        if (c + 1 < NSTGK) cp_async_wait<1>(); else cp_async_wait<0>();         \
        __syncthreads();                                                        \
        if (c + 2 < NSTGK) load_stage(c + 2, (c + 2) % 3);                      \
        const uint32_t aB = sbase + s * STG_BYTES;                              \
        const uint32_t bB = aB + OFF_B;                                         \
        _Pragma("unroll") for (int ks = 0; ks < 2; ks++) {                      \
            uint32_t af[4][4];                                                  \
            _Pragma("unroll") for (int i = 0; i < 4; i++) {                     \
                uint32_t ar = aB + (uint32_t)(warp_m * 64 + i * 16              \
                               + ((g & 1) << 3) + li) * GP                      \
                               + ks * 32 + ((uint32_t)(g >> 1) << 4);           \
                ldsm_x4(af[i], ar);                                             \
            }                                                                   \
            _Pragma("unroll") for (int j4 = 0; j4 < 2; j4++) {                  \
                uint32_t bh4[4];                                                \
                uint32_t br = bB + (uint32_t)(warp_n * 32 + j4 * 16             \
                               + ((g >> 1) << 3) + li) * GP                     \
                               + ks * 32 + ((uint32_t)(g & 1) << 4);            \
                ldsm_x4(bh4, br);                                               \
                _Pragma("unroll") for (int i = 0; i < 4; i++) {                 \
                    mma16816f(acc[i][2 * j4],     af[i], bh4 + 0);              \
                    mma16816f(acc[i][2 * j4 + 1], af[i], bh4 + 2);              \
                }                                                               \
                if (LOPASS_) {                                                  \
                    uint32_t bl4[4];                                            \
                    ldsm_x4(bl4, br + B_MAT);                                   \
                    _Pragma("unroll") for (int i = 0; i < 4; i++) {             \
                        mma16816f(acc[i][2 * j4],     af[i], bl4 + 0);          \
                        mma16816f(acc[i][2 * j4 + 1], af[i], bl4 + 2);          \
                    }                                                           \
                }                                                               \
            }                                                                   \
        }                                                                       \
    }

// --------------------------------------------------------------------------
// fused QKV projection: grid (8, 16, 3)
// which==0 -> Q hi/lo (2-pass W, pre-scaled 0.125); 1/2 -> K/V (1-pass W)
// --------------------------------------------------------------------------
__global__ void __launch_bounds__(512, 1)
gemm_qkv(const __half* __restrict__ Af, const __half* __restrict__ Whi_all,
         const __half* __restrict__ Wlo_all,
         __half* __restrict__ Qhi, __half* __restrict__ Qlo,
         __half* __restrict__ Kf, __half* __restrict__ Vf)
{
    extern __shared__ char smem[];
    const uint32_t sbase = smem_u32(smem);
    const int tid  = threadIdx.x;
    const int wid  = tid >> 5;
    const int lane = tid & 31;
    const int g    = lane >> 3;
    const int li   = lane & 7;
    const int warp_m = wid & 3;
    const int warp_n = wid >> 2;
    const int m0 = blockIdx.y * BM;
    const int n0 = blockIdx.x * BN;
    const int which = blockIdx.z;
    const bool lo_pass = (which == 0);

    const __half* Bhi = Whi_all + (size_t)which * WSZ;
    const __half* Blo = Wlo_all + (size_t)which * WSZ;

    GEMM_MAINLOOP(Af, Bhi, Blo, lo_pass)

    const int b = m0 >> 11;
    const int ncol0 = n0 + warp_n * 32;
    const int h = ncol0 >> 6;
    const int dcol = (ncol0 & 63) + 2 * (lane & 3);
#pragma unroll
    for (int i = 0; i < 4; i++) {
        int r0 = m0 + warp_m * 64 + i * 16 + (lane >> 2);
        int r1 = r0 + 8;
        size_t d0 = (((size_t)b * NUM_HEADS + h) * S_ + (r0 & (S_ - 1))) * DK + dcol;
        size_t d1 = (((size_t)b * NUM_HEADS + h) * S_ + (r1 & (S_ - 1))) * DK + dcol;
        if (which == 0) {
#pragma unroll
            for (int j = 0; j < 4; j++) {
                uint32_t hv, lv;
                pack_hl_f16(acc[i][j][0] * 0.125f, acc[i][j][1] * 0.125f, hv, lv);
                *(uint32_t*)(Qhi + d0 + 8 * j) = hv;
                *(uint32_t*)(Qlo + d0 + 8 * j) = lv;
                pack_hl_f16(acc[i][j][2] * 0.125f, acc[i][j][3] * 0.125f, hv, lv);
                *(uint32_t*)(Qhi + d1 + 8 * j) = hv;
                *(uint32_t*)(Qlo + d1 + 8 * j) = lv;
            }
        } else {
            __half* C = (which == 1) ? Kf : Vf;
#pragma unroll
            for (int j = 0; j < 4; j++) {
                *(uint32_t*)(C + d0 + 8 * j) = pack_f16(acc[i][j][0], acc[i][j][1]);
                *(uint32_t*)(C + d1 + 8 * j) = pack_f16(acc[i][j][2], acc[i][j][3]);
            }
        }
    }
}

// --------------------------------------------------------------------------
// O-projection: fp32 output; grid (8, 16); keeps 2-pass weights
// --------------------------------------------------------------------------
__global__ void __launch_bounds__(512, 1)
gemm_out(const __half* __restrict__ Af, const __half* __restrict__ Bhi,
         const __half* __restrict__ Blo, float* __restrict__ C)
{
    extern __shared__ char smem[];
    const uint32_t sbase = smem_u32(smem);
    const int tid  = threadIdx.x;
    const int wid  = tid >> 5;
    const int lane = tid & 31;
    const int g    = lane >> 3;
    const int li   = lane & 7;
    const int warp_m = wid & 3;
    const int warp_n = wid >> 2;
    const int m0 = blockIdx.y * BM;
    const int n0 = blockIdx.x * BN;

    GEMM_MAINLOOP(Af, Bhi, Blo, true)

    const int ncol = n0 + warp_n * 32 + 2 * (lane & 3);
#pragma unroll
    for (int i = 0; i < 4; i++) {
        int r0 = m0 + warp_m * 64 + i * 16 + (lane >> 2);
        float* p0 = C + (size_t)r0 * D_MODEL + ncol;
        float* p1 = p0 + 8 * D_MODEL;
#pragma unroll
        for (int j = 0; j < 4; j++) {
            *(float2*)(p0 + 8 * j) = make_float2(acc[i][j][0], acc[i][j][1]);
            *(float2*)(p1 + 8 * j) = make_float2(acc[i][j][2], acc[i][j][3]);
        }
    }
}

// ===========================================================================
// Register-resident FA2, fp16x2, 3-stage KV pipeline (unchanged from R16)
// ===========================================================================
#define QROWS 128
#define KTILE 64
#define PITCH 144
#define Q_BYTES (QROWS * PITCH)
#define KV_MAT (KTILE * PITCH)
#define KV_STG (2 * KV_MAT)
#define AT_Q 0
#define AT_KV (2 * Q_BYTES)
#define SMEM_ATTN (AT_KV + 3 * KV_STG)  // 92160

__global__ void __launch_bounds__(256)
attn_mma(const __half* __restrict__ Qhi_g, const __half* __restrict__ Qlo_g,
         const __half* __restrict__ Kf_g, const __half* __restrict__ Vf_g,
         __half* __restrict__ Af_g)
{
    extern __shared__ char smem[];
    const uint32_t sbase = smem_u32(smem);
    const int tid  = threadIdx.x;
    const int wid  = tid >> 5;
    const int lane = tid & 31;
    const int g    = lane >> 3;
    const int li   = lane & 7;

    const int bh = blockIdx.y;
    const int b  = bh >> 4;
    const int h  = bh & 15;
    const size_t hb = (size_t)bh * S_ * DK;

    const int qt = gridDim.x - 1 - blockIdx.x;
    const int q0 = qt * QROWS;
    const int wm = wid * 16;
    const int wrmax = q0 + wm + 15;

#pragma unroll
    for (int u = 0; u < 8; u++) {
        int idx = u * 256 + tid;
        int mat = idx >> 10;
        int wi  = idx & 1023;
        int r   = wi >> 3;
        int c8  = wi & 7;
        const __half* src = (mat == 0 ? Qhi_g : Qlo_g) + hb + (size_t)(q0 + r) * DK + c8 * 8;
        cp_async16(sbase + AT_Q + mat * Q_BYTES + r * PITCH + c8 * 16, src);
    }
    cp_async_commit();

    auto load_kv = [&](int kt, int s) {
        const int k0 = kt * KTILE;
        const uint32_t st = sbase + AT_KV + s * KV_STG;
#pragma unroll
        for (int u = 0; u < 4; u++) {
            int idx = u * 256 + tid;
            int mat = idx >> 9;
            int wi  = idx & 511;
            int r   = wi >> 3;
            int c8  = wi & 7;
            const __half* base = (mat == 0) ? Kf_g : Vf_g;
            cp_async16(st + mat * KV_MAT + r * PITCH + c8 * 16,
                       base + hb + (size_t)(k0 + r) * DK + c8 * 8);
        }
        cp_async_commit();
    };

    const int nkt = 2 * qt + 2;
    load_kv(0, 0);
    if (1 < nkt) load_kv(1, 1);
    if (1 < nkt) cp_async_wait<1>(); else cp_async_wait<0>();
    __syncthreads();

    uint32_t qh[4][4], ql[4][4];
    {
        const uint32_t rowb = sbase + AT_Q + (uint32_t)(wm + ((g & 1) << 3) + li) * PITCH
                              + ((uint32_t)(g >> 1) << 4);
#pragma unroll
        for (int ks = 0; ks < 4; ks++) {
            ldsm_x4(qh[ks], rowb + ks * 32);
            ldsm_x4(ql[ks], rowb + ks * 32 + Q_BYTES);
        }
    }

    float Oc[8][4];
#pragma unroll
    for (int j = 0; j < 8; j++)
#pragma unroll
        for (int e = 0; e < 4; e++) Oc[j][e] = 0.f;
    float m0v = -1e30f, m1v = -1e30f, l0v = 0.f, l1v = 0.f;

    const int r0g = q0 + wm + (lane >> 2);
    const int r1g = r0g + 8;

    for (int kt = 0; kt < nkt; kt++) {
        const int s  = kt % 3;
        const int k0 = kt * KTILE;
        if (kt + 1 < nkt) cp_async_wait<1>(); else cp_async_wait<0>();
        __syncthreads();
        if (kt + 2 < nkt) load_kv(kt + 2, (kt + 2) % 3);

        if (k0 <= wrmax) {
            const uint32_t kb = sbase + AT_KV + s * KV_STG;

            float Sc[8][4];
#pragma unroll
            for (int j = 0; j < 8; j++)
#pragma unroll
                for (int e = 0; e < 4; e++) Sc[j][e] = 0.f;

#pragma unroll
            for (int ks = 0; ks < 4; ks++) {
#pragma unroll
                for (int jp = 0; jp < 4; jp++) {
                    uint32_t k4[4];
                    uint32_t addr = kb + (uint32_t)(jp * 16 + ((g >> 1) << 3) + li) * PITCH
                                    + ks * 32 + ((uint32_t)(g & 1) << 4);
                    ldsm_x4(k4, addr);
                    mma16816f(Sc[2 * jp],     qh[ks], k4 + 0);
                    mma16816f(Sc[2 * jp],     ql[ks], k4 + 0);
                    mma16816f(Sc[2 * jp + 1], qh[ks], k4 + 2);
                    mma16816f(Sc[2 * jp + 1], ql[ks], k4 + 2);
                }
            }

            float rx0 = -1e30f, rx1 = -1e30f;
#pragma unroll
            for (int j = 0; j < 8; j++) {
                int cb = k0 + 8 * j + 2 * (lane & 3);
#pragma unroll
                for (int e = 0; e < 2; e++) {
                    float v0 = Sc[j][e];
                    float v1 = Sc[j][2 + e];
                    if (cb + e > r0g) v0 = -1e30f;
                    if (cb + e > r1g) v1 = -1e30f;
                    Sc[j][e] = v0; Sc[j][2 + e] = v1;
                    rx0 = fmaxf(rx0, v0); rx1 = fmaxf(rx1, v1);
                }
            }
            rx0 = fmaxf(rx0, __shfl_xor_sync(0xffffffffu, rx0, 1, 4));
            rx0 = fmaxf(rx0, __shfl_xor_sync(0xffffffffu, rx0, 2, 4));
            rx1 = fmaxf(rx1, __shfl_xor_sync(0xffffffffu, rx1, 1, 4));
            rx1 = fmaxf(rx1, __shfl_xor_sync(0xffffffffu, rx1, 2, 4));

            float nm0 = fmaxf(m0v, rx0), nm1 = fmaxf(m1v, rx1);
            float cr0 = __expf(m0v - nm0), cr1 = __expf(m1v - nm1);
            float s0 = 0.f, s1 = 0.f;
#pragma unroll
            for (int j = 0; j < 8; j++) {
#pragma unroll
                for (int e = 0; e < 2; e++) {
                    float p0 = __expf(Sc[j][e] - nm0);
                    float p1 = __expf(Sc[j][2 + e] - nm1);
                    Sc[j][e] = p0; Sc[j][2 + e] = p1;
                    s0 += p0; s1 += p1;
                }
            }
            s0 += __shfl_xor_sync(0xffffffffu, s0, 1, 4);
            s0 += __shfl_xor_sync(0xffffffffu, s0, 2, 4);
            s1 += __shfl_xor_sync(0xffffffffu, s1, 1, 4);
            s1 += __shfl_xor_sync(0xffffffffu, s1, 2, 4);
            l0v = l0v * cr0 + s0;  l1v = l1v * cr1 + s1;
            m0v = nm0;  m1v = nm1;
#pragma unroll
            for (int j = 0; j < 8; j++) {
                Oc[j][0] *= cr0; Oc[j][1] *= cr0;
                Oc[j][2] *= cr1; Oc[j][3] *= cr1;
            }

            uint32_t ph[4][4], pl[4][4];
#pragma unroll
            for (int ks = 0; ks < 4; ks++) {
                int j0 = 2 * ks, j1 = 2 * ks + 1;
                pack_hl_f16(Sc[j0][0], Sc[j0][1], ph[ks][0], pl[ks][0]);
                pack_hl_f16(Sc[j0][2], Sc[j0][3], ph[ks][1], pl[ks][1]);
                pack_hl_f16(Sc[j1][0], Sc[j1][1], ph[ks][2], pl[ks][2]);
                pack_hl_f16(Sc[j1][2], Sc[j1][3], ph[ks][3], pl[ks][3]);
            }

            const uint32_t vb = kb + KV_MAT;
#pragma unroll
            for (int ks = 0; ks < 4; ks++) {
#pragma unroll
                for (int jp = 0; jp < 4; jp++) {
                    uint32_t v4[4];
                    uint32_t addr = vb + (uint32_t)(ks * 16 + ((g & 1) << 3) + li) * PITCH
                                    + jp * 32 + ((uint32_t)(g >> 1) << 4);
                    ldsm_x4_t(v4, addr);
                    mma16816f(Oc[2 * jp],     ph[ks], v4 + 0);
                    mma16816f(Oc[2 * jp],     pl[ks], v4 + 0);
                    mma16816f(Oc[2 * jp + 1], ph[ks], v4 + 2);
                    mma16816f(Oc[2 * jp + 1], pl[ks], v4 + 2);
                }
            }
        }
    }
    __syncthreads();

    {
        float il0 = 1.f / l0v, il1 = 1.f / l1v;
        size_t base0 = ((size_t)b * S_ + r0g) * D_MODEL + h * DK + 2 * (lane & 3);
        size_t base1 = ((size_t)b * S_ + r1g) * D_MODEL + h * DK + 2 * (lane & 3);
#pragma unroll
        for (int j = 0; j < 8; j++) {
            *(uint32_t*)(Af_g + base0 + 8 * j) = pack_f16(Oc[j][0] * il0, Oc[j][1] * il0);
            *(uint32_t*)(Af_g + base1 + 8 * j) = pack_f16(Oc[j][2] * il1, Oc[j][3] * il1);
        }
    }
}

// ===========================================================================
// Launch
// ===========================================================================
extern "C" void kernel_launch(void* const* d_in, const int* in_sizes, int n_in,
                              void* d_out, int out_size)
{
    (void)in_sizes; (void)n_in; (void)out_size;
    const float* x  = (const float*)d_in[0];
    const float* Wq = (const float*)d_in[1];
    const float* Wk = (const float*)d_in[2];
    const float* Wv = (const float*)d_in[3];
    const float* Wo = (const float*)d_in[4];
    float* out = (float*)d_out;

    __half *pxf, *pWh, *pWl, *pAf, *pQh, *pQl, *pKf, *pVf;
    cudaGetSymbolAddress((void**)&pxf, g_xf);
    cudaGetSymbolAddress((void**)&pWh, g_Whi);
    cudaGetSymbolAddress((void**)&pWl, g_Wlo);
    cudaGetSymbolAddress((void**)&pAf, g_Af);
    cudaGetSymbolAddress((void**)&pQh, g_Qhi);
    cudaGetSymbolAddress((void**)&pQl, g_Qlo);
    cudaGetSymbolAddress((void**)&pKf, g_Kf);
    cudaGetSymbolAddress((void**)&pVf, g_Vf);

    cudaFuncSetAttribute(gemm_qkv, cudaFuncAttributeMaxDynamicSharedMemorySize, SMEM_G3);
    cudaFuncSetAttribute(gemm_out, cudaFuncAttributeMaxDynamicSharedMemorySize, SMEM_G3);
    cudaFuncSetAttribute(attn_mma, cudaFuncAttributeMaxDynamicSharedMemorySize, SMEM_ATTN);

    split_all<<<(NX4 + 4 * NW4) / 256, 256>>>(x, Wq, Wk, Wv, Wo, pxf, pWh, pWl);

    dim3 qkvgrid(D_MODEL / BN, M_ROWS / BM, 3);     // (8, 16, 3) = 384 CTAs
    gemm_qkv<<<qkvgrid, 512, SMEM_G3>>>(pxf, pWh, pWl, pQh, pQl, pKf, pVf);

    dim3 agrid(S_ / QROWS, B_ * NUM_HEADS);         // (16, 32)
    attn_mma<<<agrid, 256, SMEM_ATTN>>>(pQh, pQl, pKf, pVf, pAf);

    dim3 ogrid(D_MODEL / BN, M_ROWS / BM);          // (8, 16) = 128 CTAs
    gemm_out<<<ogrid, 512, SMEM_G3>>>(pAf, pWh + 3 * WSZ, pWl + 3 * WSZ, out);
}